// round 1
// baseline (speedup 1.0000x reference)
#include <cuda_runtime.h>
#include <cuda_bf16.h>
#include <math.h>

// Problem constants (fixed-shape problem)
#define B_ROWS 8192
#define D_DIM 256
#define N_CLASSES 512
#define ALPHA 0.1

// Scratch: class sums [N_CLASSES x D] fp32 and class counts.
__device__ float g_class_sums[N_CLASSES * D_DIM];
__device__ int   g_class_counts[N_CLASSES];

// ---------------------------------------------------------------------------
// Kernel 0: zero the scratch (graph replays require clean state each launch)
// ---------------------------------------------------------------------------
__global__ void zero_scratch_kernel() {
    int i = blockIdx.x * blockDim.x + threadIdx.x;
    if (i < N_CLASSES * D_DIM) g_class_sums[i] = 0.0f;
    if (i < N_CLASSES)         g_class_counts[i] = 0;
}

// ---------------------------------------------------------------------------
// Kernel 1: per-row L2 normalize + scatter-add into class sums.
// 4 rows per 256-thread block; 64 threads per row, float4 per thread.
// ---------------------------------------------------------------------------
__global__ void accum_kernel(const int* __restrict__ y_true,
                             const float4* __restrict__ y_pred4) {
    const int tid    = threadIdx.x;
    const int sub    = tid >> 6;    // row group within block: 0..3
    const int lane64 = tid & 63;    // 0..63, each covers 4 dims
    const int row    = blockIdx.x * 4 + sub;

    float4 v = y_pred4[row * 64 + lane64];
    float sq = v.x * v.x + v.y * v.y + v.z * v.z + v.w * v.w;

    // Reduce sum-of-squares across the 64 threads owning this row.
    #pragma unroll
    for (int o = 16; o > 0; o >>= 1)
        sq += __shfl_xor_sync(0xffffffffu, sq, o);

    __shared__ float sh_warp[8];   // one partial per warp (8 warps)
    const int warp = tid >> 5;
    if ((tid & 31) == 0) sh_warp[warp] = sq;
    __syncthreads();

    // Each row spans warps {2*sub, 2*sub+1}
    float norm2 = sh_warp[sub * 2] + sh_warp[sub * 2 + 1];
    float inv = (norm2 > 0.0f) ? rsqrtf(norm2) : 0.0f;

    int c = y_true[row];
    float* dst = &g_class_sums[c * D_DIM + lane64 * 4];
    atomicAdd(dst + 0, v.x * inv);
    atomicAdd(dst + 1, v.y * inv);
    atomicAdd(dst + 2, v.z * inv);
    atomicAdd(dst + 3, v.w * inv);
    if (lane64 == 0) atomicAdd(&g_class_counts[c], 1);
}

// ---------------------------------------------------------------------------
// Kernel 2: finalize. 1 block, 256 threads.
//   pos_sum   = sum_c ||S_c||^2
//   total_sum = sum_d (sum_c S_c[d])^2
//   n_pos     = sum_c count_c^2
// All scalar math in double (protects total - pos cancellation).
// ---------------------------------------------------------------------------
__global__ void finalize_kernel(float* __restrict__ out) {
    const int tid = threadIdx.x;   // 0..255, one column of D each

    double ps = 0.0;   // partial pos_sum for this column
    double T  = 0.0;   // column total sum_c S_c[d]
    #pragma unroll 4
    for (int c = 0; c < N_CLASSES; c++) {
        float s = g_class_sums[c * D_DIM + tid];
        ps += (double)s * (double)s;
        T  += (double)s;
    }
    double tot = T * T;

    // counts: thread tid handles classes tid and tid+256
    long long c0 = g_class_counts[tid];
    long long c1 = g_class_counts[tid + 256];
    long long np = c0 * c0 + c1 * c1;

    // Block reduction of (ps, tot, np)
    __shared__ double sh_ps[256];
    __shared__ double sh_tot[256];
    __shared__ long long sh_np[256];
    sh_ps[tid] = ps; sh_tot[tid] = tot; sh_np[tid] = np;
    __syncthreads();
    #pragma unroll
    for (int off = 128; off > 0; off >>= 1) {
        if (tid < off) {
            sh_ps[tid]  += sh_ps[tid + off];
            sh_tot[tid] += sh_tot[tid + off];
            sh_np[tid]  += sh_np[tid + off];
        }
        __syncthreads();
    }

    if (tid == 0) {
        double pos_sum   = sh_ps[0];
        double total_sum = sh_tot[0];
        double n_pos     = (double)sh_np[0];
        double n_neg     = (double)B_ROWS * (double)B_ROWS - n_pos;
        double neg_sum   = total_sum - pos_sum;
        double pos_dist  = pos_sum / n_pos;
        double neg_dist  = (n_neg > 0.0) ? (neg_sum / n_neg) : 0.0;
        double r = pos_dist - neg_dist + ALPHA;
        out[0] = (float)(r > 0.0 ? r : 0.0);
    }
}

// ---------------------------------------------------------------------------
extern "C" void kernel_launch(void* const* d_in, const int* in_sizes, int n_in,
                              void* d_out, int out_size) {
    // Identify inputs by element count (y_true: 8192 int32, y_pred: 8192*256 f32)
    const int*   y_true;
    const float* y_pred;
    if (in_sizes[0] == B_ROWS) {
        y_true = (const int*)d_in[0];
        y_pred = (const float*)d_in[1];
    } else {
        y_true = (const int*)d_in[1];
        y_pred = (const float*)d_in[0];
    }
    float* out = (float*)d_out;

    zero_scratch_kernel<<<(N_CLASSES * D_DIM + 255) / 256, 256>>>();
    accum_kernel<<<B_ROWS / 4, 256>>>(y_true, (const float4*)y_pred);
    finalize_kernel<<<1, 256>>>(out);
}

// round 2
// speedup vs baseline: 6.5772x; 6.5772x over previous
#include <cuda_runtime.h>
#include <cuda_bf16.h>
#include <math.h>

// Problem constants (fixed-shape problem)
#define B_ROWS    8192
#define D_DIM     256
#define N_CLASSES 512
#define ALPHA     0.1
#define R_REP     4          // replicas of the class-sum buffer (atomic decontention)

// Scratch. __device__ globals are zero-initialized at module load; every kernel
// below zeroes whatever it consumed, so each full pass (incl. graph replays)
// starts from a clean state with NO dedicated zeroing kernel.
__device__ float  g_class_sums[R_REP * N_CLASSES * D_DIM];
__device__ int    g_class_counts[N_CLASSES];
__device__ float  g_T[D_DIM];       // column sums  T[d] = sum_c S_c[d]
__device__ double g_ps;             // pos_sum = sum_c ||S_c||^2

// ---------------------------------------------------------------------------
// Kernel 1: per-row L2 normalize + scatter-add into replicated class sums.
// 4 rows per 256-thread block; 64 threads per row, float4 per thread.
// ---------------------------------------------------------------------------
__global__ void accum_kernel(const int* __restrict__ y_true,
                             const float4* __restrict__ y_pred4) {
    const int tid    = threadIdx.x;
    const int sub    = tid >> 6;    // row group within block: 0..3
    const int lane64 = tid & 63;    // 0..63, each covers 4 dims
    const int row    = blockIdx.x * 4 + sub;
    const int rep    = blockIdx.x & (R_REP - 1);

    float4 v = y_pred4[row * 64 + lane64];
    float sq = v.x * v.x + v.y * v.y + v.z * v.z + v.w * v.w;

    // Reduce sum-of-squares across the 64 threads owning this row.
    #pragma unroll
    for (int o = 16; o > 0; o >>= 1)
        sq += __shfl_xor_sync(0xffffffffu, sq, o);

    __shared__ float sh_warp[8];   // one partial per warp (8 warps)
    const int warp = tid >> 5;
    if ((tid & 31) == 0) sh_warp[warp] = sq;
    __syncthreads();

    // Each row spans warps {2*sub, 2*sub+1}
    float norm2 = sh_warp[sub * 2] + sh_warp[sub * 2 + 1];
    float inv = (norm2 > 0.0f) ? rsqrtf(norm2) : 0.0f;

    int c = y_true[row];
    float* dst = &g_class_sums[((size_t)rep * N_CLASSES + c) * D_DIM + lane64 * 4];
    atomicAdd(dst + 0, v.x * inv);
    atomicAdd(dst + 1, v.y * inv);
    atomicAdd(dst + 2, v.z * inv);
    atomicAdd(dst + 3, v.w * inv);
    if (lane64 == 0) atomicAdd(&g_class_counts[c], 1);
}

// ---------------------------------------------------------------------------
// Kernel 2: parallel reduce. 64 blocks x 256 threads.
// Block b handles classes [8b, 8b+8); thread d owns column d (coalesced rows).
// Sums replicas, accumulates per-column T and scalar pos_sum, and ZEROES the
// class-sum cells it consumed (replay hygiene).
// ---------------------------------------------------------------------------
__global__ void reduce_kernel() {
    const int d     = threadIdx.x;          // column 0..255
    const int cbase = blockIdx.x * 8;

    float  Tp = 0.0f;
    double ps = 0.0;
    #pragma unroll
    for (int i = 0; i < 8; i++) {
        const int c = cbase + i;
        float S = 0.0f;
        #pragma unroll
        for (int r = 0; r < R_REP; r++) {
            size_t idx = ((size_t)r * N_CLASSES + c) * D_DIM + d;
            S += g_class_sums[idx];
            g_class_sums[idx] = 0.0f;       // leave clean for next replay
        }
        Tp += S;
        ps += (double)S * (double)S;
    }

    atomicAdd(&g_T[d], Tp);                 // 64 adds per address

    // Block-reduce ps, then one fp64 atomic per block.
    __shared__ double sh_ps[256];
    sh_ps[d] = ps;
    __syncthreads();
    #pragma unroll
    for (int off = 128; off > 0; off >>= 1) {
        if (d < off) sh_ps[d] += sh_ps[d + off];
        __syncthreads();
    }
    if (d == 0) atomicAdd(&g_ps, sh_ps[0]);
}

// ---------------------------------------------------------------------------
// Kernel 3: tiny epilogue. 1 block, 256 threads.
//   total_sum = sum_d T[d]^2 ;  n_pos = sum_c count_c^2
// Zeroes g_T, g_class_counts, g_ps after consuming them.
// ---------------------------------------------------------------------------
__global__ void final_kernel(float* __restrict__ out) {
    const int t = threadIdx.x;

    float Td = g_T[t];
    g_T[t] = 0.0f;
    double tot = (double)Td * (double)Td;

    long long c0 = g_class_counts[t];        g_class_counts[t] = 0;
    long long c1 = g_class_counts[t + 256];  g_class_counts[t + 256] = 0;
    long long np = c0 * c0 + c1 * c1;

    __shared__ double    sh_tot[256];
    __shared__ long long sh_np[256];
    sh_tot[t] = tot;
    sh_np[t]  = np;
    __syncthreads();
    #pragma unroll
    for (int off = 128; off > 0; off >>= 1) {
        if (t < off) {
            sh_tot[t] += sh_tot[t + off];
            sh_np[t]  += sh_np[t + off];
        }
        __syncthreads();
    }

    if (t == 0) {
        double pos_sum = g_ps;
        g_ps = 0.0;                          // replay hygiene
        double total_sum = sh_tot[0];
        double n_pos     = (double)sh_np[0];
        double n_neg     = (double)B_ROWS * (double)B_ROWS - n_pos;
        double neg_sum   = total_sum - pos_sum;
        double pos_dist  = pos_sum / n_pos;
        double neg_dist  = (n_neg > 0.0) ? (neg_sum / n_neg) : 0.0;
        double r = pos_dist - neg_dist + ALPHA;
        out[0] = (float)(r > 0.0 ? r : 0.0);
    }
}

// ---------------------------------------------------------------------------
extern "C" void kernel_launch(void* const* d_in, const int* in_sizes, int n_in,
                              void* d_out, int out_size) {
    const int*   y_true;
    const float* y_pred;
    if (in_sizes[0] == B_ROWS) {
        y_true = (const int*)d_in[0];
        y_pred = (const float*)d_in[1];
    } else {
        y_true = (const int*)d_in[1];
        y_pred = (const float*)d_in[0];
    }
    float* out = (float*)d_out;

    accum_kernel <<<B_ROWS / 4, 256>>>(y_true, (const float4*)y_pred);
    reduce_kernel<<<N_CLASSES / 8, 256>>>();
    final_kernel <<<1, 256>>>(out);
}

// round 3
// speedup vs baseline: 7.3134x; 1.1119x over previous
#include <cuda_runtime.h>
#include <cuda_bf16.h>
#include <math.h>

#define B_ROWS    8192
#define D_DIM     256
#define N_CLASSES 512
#define ALPHA     0.1
#define R_REP     4

// Scratch (zero-initialized at load; every kernel re-zeroes what it consumed,
// so graph replays always start clean).
__device__ float4       g_cs4[R_REP * N_CLASSES * (D_DIM / 4)];  // class sums
__device__ int          g_class_counts[N_CLASSES];
__device__ double       g_ps;       // sum_c ||S_c||^2
__device__ double       g_tot;      // sum_d T_d^2
__device__ unsigned int g_ticket;

__device__ __forceinline__ void red_add_v4(float4* addr, float4 v) {
    asm volatile("red.global.add.v4.f32 [%0], {%1,%2,%3,%4};"
                 :: "l"(addr), "f"(v.x), "f"(v.y), "f"(v.z), "f"(v.w)
                 : "memory");
}

// ---------------------------------------------------------------------------
// Kernel 1: warp-per-row normalize + scatter (vector REDs, no barriers).
// 8 warps/block, 1024 blocks. Lane owns 8 consecutive dims (2 x float4).
// ---------------------------------------------------------------------------
__global__ void accum_kernel(const int* __restrict__ y_true,
                             const float4* __restrict__ y_pred4) {
    const int warp = threadIdx.x >> 5;
    const int lane = threadIdx.x & 31;
    const int row  = blockIdx.x * 8 + warp;
    const int rep  = blockIdx.x & (R_REP - 1);

    const int c = __ldg(&y_true[row]);                 // broadcast load
    float4 a = y_pred4[row * 64 + lane * 2];
    float4 b = y_pred4[row * 64 + lane * 2 + 1];

    float sq = a.x*a.x + a.y*a.y + a.z*a.z + a.w*a.w
             + b.x*b.x + b.y*b.y + b.z*b.z + b.w*b.w;
    #pragma unroll
    for (int o = 16; o > 0; o >>= 1)
        sq += __shfl_xor_sync(0xffffffffu, sq, o);

    const float inv = (sq > 0.0f) ? rsqrtf(sq) : 0.0f;
    a.x *= inv; a.y *= inv; a.z *= inv; a.w *= inv;
    b.x *= inv; b.y *= inv; b.z *= inv; b.w *= inv;

    float4* dst = &g_cs4[(rep * N_CLASSES + c) * 64 + lane * 2];
    red_add_v4(dst,     a);
    red_add_v4(dst + 1, b);
    if (lane == 0) atomicAdd(&g_class_counts[c], 1);
}

// ---------------------------------------------------------------------------
// Kernel 2: reduce + finalize (fused via ticket). 64 blocks x 256 threads.
// Block b owns columns [4b, 4b+4) (one float4 slot). Thread t covers classes
// t and t+256 (all 512 classes per block) -> block computes its full T4 and
// local contributions to pos_sum and total_sum with ZERO cross-block column
// atomics. Last block to finish runs the scalar epilogue.
// ---------------------------------------------------------------------------
__global__ void reduce_final_kernel(float* __restrict__ out) {
    const int t = threadIdx.x;
    const int b = blockIdx.x;            // float4 column slot

    float4 T4 = make_float4(0.f, 0.f, 0.f, 0.f);
    double ps = 0.0;

    #pragma unroll
    for (int cc = 0; cc < 2; cc++) {
        const int c = t + cc * 256;
        float4 S = make_float4(0.f, 0.f, 0.f, 0.f);
        #pragma unroll
        for (int r = 0; r < R_REP; r++) {
            const int idx = (r * N_CLASSES + c) * 64 + b;
            float4 v = g_cs4[idx];
            g_cs4[idx] = make_float4(0.f, 0.f, 0.f, 0.f);   // replay hygiene
            S.x += v.x; S.y += v.y; S.z += v.z; S.w += v.w;
        }
        T4.x += S.x; T4.y += S.y; T4.z += S.z; T4.w += S.w;
        ps += (double)S.x * S.x + (double)S.y * S.y
            + (double)S.z * S.z + (double)S.w * S.w;
    }

    __shared__ float4 shT[256];
    __shared__ double shP[256];
    shT[t] = T4; shP[t] = ps;
    __syncthreads();
    #pragma unroll
    for (int off = 128; off > 0; off >>= 1) {
        if (t < off) {
            float4 o4 = shT[t + off];
            shT[t].x += o4.x; shT[t].y += o4.y; shT[t].z += o4.z; shT[t].w += o4.w;
            shP[t] += shP[t + off];
        }
        __syncthreads();
    }

    __shared__ int isLast;
    if (t == 0) {
        float4 T = shT[0];
        double tot = (double)T.x * T.x + (double)T.y * T.y
                   + (double)T.z * T.z + (double)T.w * T.w;
        atomicAdd(&g_ps,  shP[0]);
        atomicAdd(&g_tot, tot);
        __threadfence();
        unsigned tk = atomicAdd(&g_ticket, 1u);
        isLast = (tk == gridDim.x - 1) ? 1 : 0;
    }
    __syncthreads();

    if (isLast) {
        long long c0 = g_class_counts[t];        g_class_counts[t] = 0;
        long long c1 = g_class_counts[t + 256];  g_class_counts[t + 256] = 0;
        long long np = c0 * c0 + c1 * c1;

        __shared__ long long shN[256];
        shN[t] = np;
        __syncthreads();
        #pragma unroll
        for (int off = 128; off > 0; off >>= 1) {
            if (t < off) shN[t] += shN[t + off];
            __syncthreads();
        }

        if (t == 0) {
            // Atomic reads guarantee we see the L2-resident accumulators.
            double pos_sum   = atomicAdd(&g_ps,  0.0);
            double total_sum = atomicAdd(&g_tot, 0.0);
            g_ps = 0.0; g_tot = 0.0; g_ticket = 0u;   // replay hygiene

            double n_pos   = (double)shN[0];
            double n_neg   = (double)B_ROWS * (double)B_ROWS - n_pos;
            double neg_sum = total_sum - pos_sum;
            double pos_d   = pos_sum / n_pos;
            double neg_d   = (n_neg > 0.0) ? (neg_sum / n_neg) : 0.0;
            double r = pos_d - neg_d + ALPHA;
            out[0] = (float)(r > 0.0 ? r : 0.0);
        }
    }
}

// ---------------------------------------------------------------------------
extern "C" void kernel_launch(void* const* d_in, const int* in_sizes, int n_in,
                              void* d_out, int out_size) {
    const int*   y_true;
    const float* y_pred;
    if (in_sizes[0] == B_ROWS) {
        y_true = (const int*)d_in[0];
        y_pred = (const float*)d_in[1];
    } else {
        y_true = (const int*)d_in[1];
        y_pred = (const float*)d_in[0];
    }
    float* out = (float*)d_out;

    accum_kernel<<<B_ROWS / 8, 256>>>(y_true, (const float4*)y_pred);
    reduce_final_kernel<<<64, 256>>>(out);
}